// round 2
// baseline (speedup 1.0000x reference)
#include <cuda_runtime.h>
#include <cuda_bf16.h>
#include <math.h>

// Problem constants
#define IMGS 48
#define H 512
#define W 512
#define IMG_ELEMS (H * W)            // 262144
#define VALID 506                    // 512 - 7 + 1
#define N_TOTAL (48.0 * 512.0 * 512.0)
#define N_SSIM  (48.0 * 506.0 * 506.0)

// Tile config for k_ssim: 64x32 outputs per block, halo 70x38.
#define TW 64
#define TH 32
#define HW 70          // TW + 6
#define HH 38          // TH + 6
#define SXP 73         // sx/sy row pitch (stride 73 -> bank step 9, conflict-free)
#define HSP 65         // hs row pitch   (stride 65 -> bank step 1, conflict-free)
#define GRID_X 8       // 512 / 64
#define GRID_Y 16      // 512 / 32
#define NBLK (GRID_X * GRID_Y * IMGS)   // 6144

#define RANGE_BLKS_PER_IMG 16

// Scratch (device globals — no allocation allowed)
__device__ float g_pabs[NBLK];
__device__ float g_psq[NBLK];
__device__ float g_pS[NBLK];
__device__ float g_pmin[IMGS * RANGE_BLKS_PER_IMG];
__device__ float g_pmax[IMGS * RANGE_BLKS_PER_IMG];

// ---------------------------------------------------------------------------
// Kernel 1: per-image min/max of y_true*mask (partials, no atomics, no init)
// 16 blocks/image x 256 threads x 16 float4.
// ---------------------------------------------------------------------------
__global__ void __launch_bounds__(256) k_range(
    const float4* __restrict__ t4, const float4* __restrict__ m4)
{
    int img = blockIdx.x >> 4;
    int blk = blockIdx.x & 15;
    long base = (long)img * (IMG_ELEMS / 4) + (long)blk * 4096;

    float mn = INFINITY, mx = -INFINITY;
#pragma unroll
    for (int i = 0; i < 16; i++) {
        long idx = base + threadIdx.x + i * 256;
        float4 t = t4[idx];
        float4 m = m4[idx];
        float y0 = t.x * m.x, y1 = t.y * m.y, y2 = t.z * m.z, y3 = t.w * m.w;
        mn = fminf(mn, fminf(fminf(y0, y1), fminf(y2, y3)));
        mx = fmaxf(mx, fmaxf(fmaxf(y0, y1), fmaxf(y2, y3)));
    }
#pragma unroll
    for (int o = 16; o; o >>= 1) {
        mn = fminf(mn, __shfl_down_sync(0xffffffffu, mn, o));
        mx = fmaxf(mx, __shfl_down_sync(0xffffffffu, mx, o));
    }
    __shared__ float wmn[8], wmx[8];
    int lane = threadIdx.x & 31, w = threadIdx.x >> 5;
    if (lane == 0) { wmn[w] = mn; wmx[w] = mx; }
    __syncthreads();
    if (threadIdx.x == 0) {
        float MN = INFINITY, MX = -INFINITY;
#pragma unroll
        for (int i = 0; i < 8; i++) {
            MN = fminf(MN, wmn[i]);
            MX = fmaxf(MX, wmx[i]);
        }
        g_pmin[blockIdx.x] = MN;
        g_pmax[blockIdx.x] = MX;
    }
}

// ---------------------------------------------------------------------------
// Kernel 2: fused SSIM + MAE/MSE.
// Block = 64x32 output tile (70x38 halo). Dynamic smem:
//   sx[38][73], sy[38][73], hs[5][38][65], scratch[28]
// h-pass: each thread emits 8 h-sums from a 14-wide register sliding window.
// v-pass: 8 rows/thread with a 7-deep register ring buffer.
// MAE/MSE accumulated during halo load over the block's exclusive 64x32 region.
// ---------------------------------------------------------------------------
#define SX_OFF 0
#define SY_OFF (HH * SXP)                 // 2774
#define HS_OFF (2 * HH * SXP)             // 5548
#define HS_PLANE (HH * HSP)               // 2470
#define SCR_OFF (HS_OFF + 5 * HS_PLANE)   // 17898
#define SMEM_FLOATS (SCR_OFF + 32)

__global__ void __launch_bounds__(256) k_ssim(
    const float* __restrict__ P, const float* __restrict__ T,
    const float* __restrict__ M)
{
    extern __shared__ float sm[];
    float* sxp = sm + SX_OFF;
    float* syp = sm + SY_OFF;
    float* hsp = sm + HS_OFF;
    float* scr = sm + SCR_OFF;

    int img = blockIdx.z;
    int ox0 = blockIdx.x * TW;
    int oy0 = blockIdx.y * TH;
    int tid = threadIdx.x;

    // ---- C1/C2 from range partials (lanes 0..15 of warp 0) ----
    if (tid < 16) {
        float mn = g_pmin[img * RANGE_BLKS_PER_IMG + tid];
        float mx = g_pmax[img * RANGE_BLKS_PER_IMG + tid];
#pragma unroll
        for (int o = 8; o; o >>= 1) {
            mn = fminf(mn, __shfl_down_sync(0xffffu, mn, o));
            mx = fmaxf(mx, __shfl_down_sync(0xffffu, mx, o));
        }
        if (tid == 0) {
            float d = mx - mn;
            float c1 = 0.01f * d, c2 = 0.03f * d;
            scr[24] = c1 * c1;
            scr[25] = c2 * c2;
        }
    }

    const float* Pi = P + (size_t)img * IMG_ELEMS;
    const float* Ti = T + (size_t)img * IMG_ELEMS;
    const float* Mi = M + (size_t)img * IMG_ELEMS;

    // ---- Halo load + MAE/MSE over owned region ----
    float sa = 0.f, sq = 0.f;
    for (int l = tid; l < HW * HH; l += 256) {
        int r = l / HW, c = l - r * HW;
        int gy = min(oy0 + r, H - 1);
        int gx = min(ox0 + c, W - 1);
        int g = gy * W + gx;
        float m = Mi[g];
        float x = Pi[g] * m;
        float y = Ti[g] * m;
        sxp[r * SXP + c] = x;
        syp[r * SXP + c] = y;
        if (r < TH && c < TW) {          // exclusive ownership: tiles the image
            float d = x - y;
            sa += fabsf(d);
            sq += d * d;
        }
    }
    __syncthreads();

    // ---- Horizontal 7-tap pass: 38 rows x 8 chunks of 8 outputs ----
    for (int l = tid; l < HH * (TW / 8); l += 256) {
        int chunk = l / HH;              // 0..7
        int r = l - chunk * HH;          // 0..37
        int ib = r * SXP + chunk * 8;
        float xw[14], yw[14];
#pragma unroll
        for (int j = 0; j < 14; j++) {
            xw[j] = sxp[ib + j];
            yw[j] = syp[ib + j];
        }
        float s0 = 0.f, s1 = 0.f, s2 = 0.f, s3 = 0.f, s4 = 0.f;
#pragma unroll
        for (int j = 0; j < 7; j++) {
            s0 += xw[j]; s1 += yw[j];
            s2 += xw[j] * xw[j]; s3 += yw[j] * yw[j]; s4 += xw[j] * yw[j];
        }
        int ob = r * HSP + chunk * 8;
        hsp[0 * HS_PLANE + ob] = s0;
        hsp[1 * HS_PLANE + ob] = s1;
        hsp[2 * HS_PLANE + ob] = s2;
        hsp[3 * HS_PLANE + ob] = s3;
        hsp[4 * HS_PLANE + ob] = s4;
#pragma unroll
        for (int j = 1; j < 8; j++) {
            float xa = xw[6 + j], ya = yw[6 + j];
            float xd = xw[j - 1], yd = yw[j - 1];
            s0 += xa - xd;
            s1 += ya - yd;
            s2 += xa * xa - xd * xd;
            s3 += ya * ya - yd * yd;
            s4 += xa * ya - xd * yd;
            hsp[0 * HS_PLANE + ob + j] = s0;
            hsp[1 * HS_PLANE + ob + j] = s1;
            hsp[2 * HS_PLANE + ob + j] = s2;
            hsp[3 * HS_PLANE + ob + j] = s3;
            hsp[4 * HS_PLANE + ob + j] = s4;
        }
    }
    __syncthreads();

    // ---- Vertical pass: thread (tx, ty) -> col tx, rows ty*8 .. ty*8+7 ----
    int tx = tid & 63;
    int ty = tid >> 6;
    int r0 = ty * 8;

    float C1 = scr[24], C2 = scr[25];
    float b[5][7], s[5];
#pragma unroll
    for (int q = 0; q < 5; q++) { s[q] = 0.f; b[q][6] = 0.f; }
#pragma unroll
    for (int j = 0; j < 6; j++) {
#pragma unroll
        for (int q = 0; q < 5; q++) {
            float v = hsp[q * HS_PLANE + (r0 + j) * HSP + tx];
            b[q][j] = v;
            s[q] += v;
        }
    }

    const float inv = 1.f / 49.f;
    const float cov = 49.f / 48.f;
    float lsum = 0.f;
    int gx = ox0 + tx;

#pragma unroll
    for (int i = 0; i < 8; i++) {
        int slot = (6 + i) % 7;
#pragma unroll
        for (int q = 0; q < 5; q++) {
            float v = hsp[q * HS_PLANE + (r0 + 6 + i) * HSP + tx];
            s[q] += v - b[q][slot];
            b[q][slot] = v;
        }
        int gy = oy0 + r0 + i;
        if (gx < VALID && gy < VALID) {
            float ux = s[0] * inv, uy = s[1] * inv;
            float vx  = cov * (s[2] * inv - ux * ux);
            float vy  = cov * (s[3] * inv - uy * uy);
            float vxy = cov * (s[4] * inv - ux * uy);
            float A1 = 2.f * ux * uy + C1;
            float A2 = 2.f * vxy + C2;
            float B1 = ux * ux + uy * uy + C1;
            float B2 = vx + vy + C2;
            lsum += __fdividef(A1 * A2, B1 * B2);
        }
    }

    // ---- Block reduce (sa, sq, lsum) -> partial stores ----
#pragma unroll
    for (int o = 16; o; o >>= 1) {
        sa += __shfl_down_sync(0xffffffffu, sa, o);
        sq += __shfl_down_sync(0xffffffffu, sq, o);
        lsum += __shfl_down_sync(0xffffffffu, lsum, o);
    }
    int lane = tid & 31, w = tid >> 5;
    if (lane == 0) { scr[w] = sa; scr[8 + w] = sq; scr[16 + w] = lsum; }
    __syncthreads();
    if (tid == 0) {
        float A = 0.f, Q = 0.f, S = 0.f;
#pragma unroll
        for (int i = 0; i < 8; i++) { A += scr[i]; Q += scr[8 + i]; S += scr[16 + i]; }
        int bid = blockIdx.x + (blockIdx.y << 3) + (blockIdx.z << 7);
        g_pabs[bid] = A;
        g_psq[bid] = Q;
        g_pS[bid] = S;
    }
}

// ---------------------------------------------------------------------------
// Kernel 3: final reduction of 6144 partials (double) -> 4 outputs
// ---------------------------------------------------------------------------
__global__ void __launch_bounds__(256) k_final(float* __restrict__ out) {
    int tid = threadIdx.x;
    double a = 0.0, q = 0.0, s = 0.0;
    for (int i = tid; i < NBLK; i += 256) {
        a += (double)g_pabs[i];
        q += (double)g_psq[i];
        s += (double)g_pS[i];
    }
#pragma unroll
    for (int o = 16; o; o >>= 1) {
        a += __shfl_down_sync(0xffffffffu, a, o);
        q += __shfl_down_sync(0xffffffffu, q, o);
        s += __shfl_down_sync(0xffffffffu, s, o);
    }
    __shared__ double wa[8], wq[8], ws[8];
    int lane = tid & 31, w = tid >> 5;
    if (lane == 0) { wa[w] = a; wq[w] = q; ws[w] = s; }
    __syncthreads();
    if (tid == 0) {
        double A = 0.0, Q = 0.0, S = 0.0;
#pragma unroll
        for (int i = 0; i < 8; i++) { A += wa[i]; Q += wq[i]; S += ws[i]; }
        double mae = A / N_TOTAL;
        double mse = Q / N_TOTAL;
        double ssim_loss = 1.0 - S / N_SSIM;
        double total = mae + 0.5 * mse + 0.2 * ssim_loss;
        out[0] = (float)total;
        out[1] = (float)mae;
        out[2] = (float)mse;
        out[3] = (float)ssim_loss;
    }
}

// ---------------------------------------------------------------------------
extern "C" void kernel_launch(void* const* d_in, const int* in_sizes, int n_in,
                              void* d_out, int out_size)
{
    const float* y_pred = (const float*)d_in[0];
    const float* y_true = (const float*)d_in[1];
    const float* mask   = (const float*)d_in[2];
    float* out = (float*)d_out;

    static_assert(SMEM_FLOATS * 4 < 80 * 1024, "smem budget");
    cudaFuncSetAttribute(k_ssim, cudaFuncAttributeMaxDynamicSharedMemorySize,
                         SMEM_FLOATS * 4);

    k_range<<<IMGS * RANGE_BLKS_PER_IMG, 256>>>((const float4*)y_true,
                                                (const float4*)mask);
    dim3 grid(GRID_X, GRID_Y, IMGS);
    k_ssim<<<grid, 256, SMEM_FLOATS * 4>>>(y_pred, y_true, mask);
    k_final<<<1, 256>>>(out);
}

// round 3
// speedup vs baseline: 1.0103x; 1.0103x over previous
#include <cuda_runtime.h>
#include <cuda_bf16.h>
#include <math.h>

// Problem constants
#define IMGS 48
#define H 512
#define W 512
#define IMG_ELEMS (H * W)
#define VALID 506
#define N_TOTAL (48.0 * 512.0 * 512.0)
#define N_SSIM  (48.0 * 506.0 * 506.0)

// k_ssim tile: 64 wide x 32 high outputs; halo 70x38 inputs.
#define TW 64
#define TH 32
#define HW 70
#define HH 38
#define P2 71          // float2 pitch for sxy  (bank-stride 14 over 16-lane phase: distinct)
#define P4 65          // float4 pitch for hs4  (odd -> distinct 128b bank-groups)
#define P1 65          // float  pitch for hs1
#define GRID_X 8
#define GRID_Y 16
#define NBLK (GRID_X * GRID_Y * IMGS)    // 6144

#define RB 32          // range blocks per image

// Device scratch
__device__ float g_pabs[NBLK];
__device__ float g_psq[NBLK];
__device__ float g_pS[NBLK];
__device__ float g_pmin[IMGS * RB];
__device__ float g_pmax[IMGS * RB];

// ---------------------------------------------------------------------------
// Kernel 1: per-image min/max of y_true*mask. 32 blocks/img x 256 thr x 8 f4.
// ---------------------------------------------------------------------------
__global__ void __launch_bounds__(256) k_range(
    const float4* __restrict__ t4, const float4* __restrict__ m4)
{
    int img = blockIdx.x >> 5;
    int blk = blockIdx.x & 31;
    long base = (long)img * (IMG_ELEMS / 4) + (long)blk * 2048;

    float mn = INFINITY, mx = -INFINITY;
#pragma unroll
    for (int i = 0; i < 8; i++) {
        long idx = base + threadIdx.x + i * 256;
        float4 t = t4[idx];
        float4 m = m4[idx];
        float y0 = t.x * m.x, y1 = t.y * m.y, y2 = t.z * m.z, y3 = t.w * m.w;
        mn = fminf(mn, fminf(fminf(y0, y1), fminf(y2, y3)));
        mx = fmaxf(mx, fmaxf(fmaxf(y0, y1), fmaxf(y2, y3)));
    }
#pragma unroll
    for (int o = 16; o; o >>= 1) {
        mn = fminf(mn, __shfl_down_sync(0xffffffffu, mn, o));
        mx = fmaxf(mx, __shfl_down_sync(0xffffffffu, mx, o));
    }
    __shared__ float wmn[8], wmx[8];
    int lane = threadIdx.x & 31, w = threadIdx.x >> 5;
    if (lane == 0) { wmn[w] = mn; wmx[w] = mx; }
    __syncthreads();
    if (threadIdx.x == 0) {
        float MN = INFINITY, MX = -INFINITY;
#pragma unroll
        for (int i = 0; i < 8; i++) {
            MN = fminf(MN, wmn[i]);
            MX = fmaxf(MX, wmx[i]);
        }
        g_pmin[blockIdx.x] = MN;
        g_pmax[blockIdx.x] = MX;
    }
}

// ---------------------------------------------------------------------------
// Kernel 2: fused SSIM + MAE/MSE, division-free warp-aligned mappings.
// smem: sxy float2[38][71], hs4 float4[38][65], hs1 float[38][65], scr[32]
// ---------------------------------------------------------------------------
#define SXY_F (HH * P2 * 2)              // floats in sxy
#define HS4_F (HH * P4 * 4)
#define HS1_F (HH * P1)
#define SMEM_FLOATS (SXY_F + HS4_F + HS1_F + 32)

__global__ void __launch_bounds__(256) k_ssim(
    const float* __restrict__ P, const float* __restrict__ T,
    const float* __restrict__ M)
{
    extern __shared__ float sm[];
    float2* sxy = (float2*)sm;                       // [38][71]
    float4* hs4 = (float4*)(sm + SXY_F);             // [38][65]
    float*  hs1 = sm + SXY_F + HS4_F;                // [38][65]
    float*  scr = sm + SXY_F + HS4_F + HS1_F;

    int img = blockIdx.z;
    int ox0 = blockIdx.x * TW;
    int oy0 = blockIdx.y * TH;
    int tid = threadIdx.x;
    int lane = tid & 31;
    int warp = tid >> 5;

    // ---- C1/C2 from 32 range partials (warp 0) ----
    if (warp == 0) {
        float mn = g_pmin[img * RB + lane];
        float mx = g_pmax[img * RB + lane];
#pragma unroll
        for (int o = 16; o; o >>= 1) {
            mn = fminf(mn, __shfl_down_sync(0xffffffffu, mn, o));
            mx = fmaxf(mx, __shfl_down_sync(0xffffffffu, mx, o));
        }
        if (lane == 0) {
            float d = mx - mn;
            float c1 = 0.01f * d, c2 = 0.03f * d;
            scr[24] = c1 * c1;
            scr[25] = c2 * c2;
        }
    }

    const float* Pi = P + (size_t)img * IMG_ELEMS;
    const float* Ti = T + (size_t)img * IMG_ELEMS;
    const float* Mi = M + (size_t)img * IMG_ELEMS;

    // ---- Halo load (70x38) + MAE/MSE over exclusive 64x32 region ----
    float sa = 0.f, sq = 0.f;
    {
        int tx = tid & 63;             // col 0..63
        int ty = tid >> 6;             // row group 0..3
        int gx = min(ox0 + tx, W - 1);
        int gx2 = min(ox0 + 64 + tx, W - 1);   // cols 64..69 (tx<6)
#pragma unroll 1
        for (int r = ty; r < HH; r += 4) {
            int gy = min(oy0 + r, H - 1);
            int rowb = gy * W;
            float m = Mi[rowb + gx];
            float x = Pi[rowb + gx] * m;
            float y = Ti[rowb + gx] * m;
            sxy[r * P2 + tx] = make_float2(x, y);
            if (r < TH) {
                float d = x - y;
                sa += fabsf(d);
                sq += d * d;
            }
            if (tx < 6) {
                float m2 = Mi[rowb + gx2];
                float x2 = Pi[rowb + gx2] * m2;
                float y2 = Ti[rowb + gx2] * m2;
                sxy[r * P2 + 64 + tx] = make_float2(x2, y2);
            }
        }
    }
    __syncthreads();

    // ---- Horizontal pass: warp w -> chunk of 8 output cols, lanes -> rows ----
    // rows 0..31 (all lanes), then 32..37 (lanes < 6)
    {
        int cbase = warp * 8;
#pragma unroll 1
        for (int pass = 0; pass < 2; pass++) {
            int r = pass == 0 ? lane : 32 + lane;
            if (pass == 1 && lane >= 6) break;
            const float2* row = sxy + r * P2 + cbase;
            float2 wv[14];
#pragma unroll
            for (int j = 0; j < 14; j++) wv[j] = row[j];
            float s0 = 0.f, s1 = 0.f, s2 = 0.f, s3 = 0.f, s4 = 0.f;
#pragma unroll
            for (int j = 0; j < 7; j++) {
                float x = wv[j].x, y = wv[j].y;
                s0 += x; s1 += y; s2 += x * x; s3 += y * y; s4 += x * y;
            }
            float4* o4 = hs4 + r * P4 + cbase;
            float*  o1 = hs1 + r * P1 + cbase;
            o4[0] = make_float4(s0, s1, s2, s3);
            o1[0] = s4;
#pragma unroll
            for (int j = 1; j < 8; j++) {
                float xa = wv[6 + j].x, ya = wv[6 + j].y;
                float xd = wv[j - 1].x, yd = wv[j - 1].y;
                s0 += xa - xd;
                s1 += ya - yd;
                s2 += xa * xa - xd * xd;
                s3 += ya * ya - yd * yd;
                s4 += xa * ya - xd * yd;
                o4[j] = make_float4(s0, s1, s2, s3);
                o1[j] = s4;
            }
        }
    }
    __syncthreads();

    // ---- Vertical pass: thread (tx, ty) -> col tx, rows ty*8..ty*8+7 ----
    int tx = tid & 63;
    int ty = tid >> 6;
    int r0 = ty * 8;

    float C1 = scr[24], C2 = scr[25];
    float4 b4[7]; float b1[7];
    float t0 = 0.f, t1 = 0.f, t2 = 0.f, t3 = 0.f, t4 = 0.f;
    b4[6] = make_float4(0.f, 0.f, 0.f, 0.f); b1[6] = 0.f;
#pragma unroll
    for (int j = 0; j < 6; j++) {
        float4 v = hs4[(r0 + j) * P4 + tx];
        float  u = hs1[(r0 + j) * P1 + tx];
        b4[j] = v; b1[j] = u;
        t0 += v.x; t1 += v.y; t2 += v.z; t3 += v.w; t4 += u;
    }

    const float inv = 1.f / 49.f;
    const float cov = 49.f / 48.f;
    float lsum = 0.f;
    int gox = ox0 + tx;

#pragma unroll
    for (int i = 0; i < 8; i++) {
        int slot = (6 + i) % 7;
        float4 v = hs4[(r0 + 6 + i) * P4 + tx];
        float  u = hs1[(r0 + 6 + i) * P1 + tx];
        t0 += v.x - b4[slot].x;
        t1 += v.y - b4[slot].y;
        t2 += v.z - b4[slot].z;
        t3 += v.w - b4[slot].w;
        t4 += u - b1[slot];
        b4[slot] = v; b1[slot] = u;
        int goy = oy0 + r0 + i;
        if (gox < VALID && goy < VALID) {
            float ux = t0 * inv, uy = t1 * inv;
            float vx  = cov * (t2 * inv - ux * ux);
            float vy  = cov * (t3 * inv - uy * uy);
            float vxy = cov * (t4 * inv - ux * uy);
            float A1 = 2.f * ux * uy + C1;
            float A2 = 2.f * vxy + C2;
            float B1 = ux * ux + uy * uy + C1;
            float B2 = vx + vy + C2;
            lsum += __fdividef(A1 * A2, B1 * B2);
        }
    }

    // ---- Block reduce (sa, sq, lsum) -> partial stores ----
#pragma unroll
    for (int o = 16; o; o >>= 1) {
        sa += __shfl_down_sync(0xffffffffu, sa, o);
        sq += __shfl_down_sync(0xffffffffu, sq, o);
        lsum += __shfl_down_sync(0xffffffffu, lsum, o);
    }
    __syncthreads();   // hs reads done before scr reuse
    if (lane == 0) { scr[warp] = sa; scr[8 + warp] = sq; scr[16 + warp] = lsum; }
    __syncthreads();
    if (tid == 0) {
        float A = 0.f, Q = 0.f, S = 0.f;
#pragma unroll
        for (int i = 0; i < 8; i++) { A += scr[i]; Q += scr[8 + i]; S += scr[16 + i]; }
        int bid = blockIdx.x + (blockIdx.y << 3) + (blockIdx.z << 7);
        g_pabs[bid] = A;
        g_psq[bid] = Q;
        g_pS[bid] = S;
    }
}

// ---------------------------------------------------------------------------
// Kernel 3: final reduction of 6144 partials (double) -> 4 outputs
// ---------------------------------------------------------------------------
__global__ void __launch_bounds__(256) k_final(float* __restrict__ out) {
    int tid = threadIdx.x;
    double a = 0.0, q = 0.0, s = 0.0;
    for (int i = tid; i < NBLK; i += 256) {
        a += (double)g_pabs[i];
        q += (double)g_psq[i];
        s += (double)g_pS[i];
    }
#pragma unroll
    for (int o = 16; o; o >>= 1) {
        a += __shfl_down_sync(0xffffffffu, a, o);
        q += __shfl_down_sync(0xffffffffu, q, o);
        s += __shfl_down_sync(0xffffffffu, s, o);
    }
    __shared__ double wa[8], wq[8], ws[8];
    int lane = tid & 31, w = tid >> 5;
    if (lane == 0) { wa[w] = a; wq[w] = q; ws[w] = s; }
    __syncthreads();
    if (tid == 0) {
        double A = 0.0, Q = 0.0, S = 0.0;
#pragma unroll
        for (int i = 0; i < 8; i++) { A += wa[i]; Q += wq[i]; S += ws[i]; }
        double mae = A / N_TOTAL;
        double mse = Q / N_TOTAL;
        double ssim_loss = 1.0 - S / N_SSIM;
        double total = mae + 0.5 * mse + 0.2 * ssim_loss;
        out[0] = (float)total;
        out[1] = (float)mae;
        out[2] = (float)mse;
        out[3] = (float)ssim_loss;
    }
}

// ---------------------------------------------------------------------------
extern "C" void kernel_launch(void* const* d_in, const int* in_sizes, int n_in,
                              void* d_out, int out_size)
{
    const float* y_pred = (const float*)d_in[0];
    const float* y_true = (const float*)d_in[1];
    const float* mask   = (const float*)d_in[2];
    float* out = (float*)d_out;

    cudaFuncSetAttribute(k_ssim, cudaFuncAttributeMaxDynamicSharedMemorySize,
                         SMEM_FLOATS * 4);

    k_range<<<IMGS * RB, 256>>>((const float4*)y_true, (const float4*)mask);
    dim3 grid(GRID_X, GRID_Y, IMGS);
    k_ssim<<<grid, 256, SMEM_FLOATS * 4>>>(y_pred, y_true, mask);
    k_final<<<1, 256>>>(out);
}

// round 5
// speedup vs baseline: 1.4132x; 1.3988x over previous
#include <cuda_runtime.h>
#include <cuda_bf16.h>
#include <math.h>

// Problem constants
#define IMGS 48
#define H 512
#define W 512
#define IMG_ELEMS (H * W)
#define VALID 506
#define N_TOTAL (48.0 * 512.0 * 512.0)
#define N_SSIM  (48.0 * 506.0 * 506.0)

// k_ssim tile: 64x32 outputs, halo 70x38 (72 cols loaded as 36 float2 pairs).
#define TW 64
#define TH 32
#define HH 38
#define PSXY 37         // sxy pitch in float4 (36 pairs + 1 pad); 37%8=5, gcd(5,8)=1 -> conflict-free
#define P4 65           // hs4 pitch (float4)
#define P1 65           // hs1 pitch (float)
#define GRID_X 8
#define GRID_Y 16
#define NBLK (GRID_X * GRID_Y * IMGS)    // 6144
#define RB 32           // range blocks per image

// smem layout (floats)
#define SXY_F (HH * PSXY * 4)            // 5624
#define HS4_F (HH * P4 * 4)              // 9880
#define HS1_F (HH * P1)                  // 2470
#define SMEM_FLOATS (SXY_F + HS4_F + HS1_F + 32)   // 18006 -> 72.0 KB

// Device scratch
__device__ float g_pabs[NBLK];
__device__ float g_psq[NBLK];
__device__ float g_pS[NBLK];
__device__ float g_pmin[IMGS * RB];
__device__ float g_pmax[IMGS * RB];

// ---------------------------------------------------------------------------
// Kernel 1: per-image min/max of y_true*mask. 32 blocks/img x 256 thr x 8 f4.
// ---------------------------------------------------------------------------
__global__ void __launch_bounds__(256) k_range(
    const float4* __restrict__ t4, const float4* __restrict__ m4)
{
    int img = blockIdx.x >> 5;
    int blk = blockIdx.x & 31;
    long base = (long)img * (IMG_ELEMS / 4) + (long)blk * 2048;

    float mn = INFINITY, mx = -INFINITY;
#pragma unroll
    for (int i = 0; i < 8; i++) {
        long idx = base + threadIdx.x + i * 256;
        float4 t = t4[idx];
        float4 m = m4[idx];
        float y0 = t.x * m.x, y1 = t.y * m.y, y2 = t.z * m.z, y3 = t.w * m.w;
        mn = fminf(mn, fminf(fminf(y0, y1), fminf(y2, y3)));
        mx = fmaxf(mx, fmaxf(fmaxf(y0, y1), fmaxf(y2, y3)));
    }
#pragma unroll
    for (int o = 16; o; o >>= 1) {
        mn = fminf(mn, __shfl_down_sync(0xffffffffu, mn, o));
        mx = fmaxf(mx, __shfl_down_sync(0xffffffffu, mx, o));
    }
    __shared__ float wmn[8], wmx[8];
    int lane = threadIdx.x & 31, w = threadIdx.x >> 5;
    if (lane == 0) { wmn[w] = mn; wmx[w] = mx; }
    __syncthreads();
    if (threadIdx.x == 0) {
        float MN = INFINITY, MX = -INFINITY;
#pragma unroll
        for (int i = 0; i < 8; i++) {
            MN = fminf(MN, wmn[i]);
            MX = fmaxf(MX, wmx[i]);
        }
        g_pmin[blockIdx.x] = MN;
        g_pmax[blockIdx.x] = MX;
    }
}

// ---------------------------------------------------------------------------
// Kernel 2: fused SSIM + MAE/MSE. High-MLP vectorized halo load.
// ---------------------------------------------------------------------------
__global__ void __launch_bounds__(256) k_ssim(
    const float* __restrict__ P, const float* __restrict__ T,
    const float* __restrict__ M)
{
    extern __shared__ float sm[];
    float4* sxy = (float4*)sm;                       // [38][37] : (x0,y0,x1,y1)
    float4* hs4 = (float4*)(sm + SXY_F);             // [38][65] : (s0,s1,s2,s3)
    float*  hs1 = sm + SXY_F + HS4_F;                // [38][65] : s4
    float*  scr = sm + SXY_F + HS4_F + HS1_F;

    int img = blockIdx.z;
    int ox0 = blockIdx.x * TW;
    int oy0 = blockIdx.y * TH;
    int tid = threadIdx.x;
    int lane = tid & 31;
    int warp = tid >> 5;

    // ---- C1/C2 from 32 range partials (warp 0) ----
    if (warp == 0) {
        float mn = g_pmin[img * RB + lane];
        float mx = g_pmax[img * RB + lane];
#pragma unroll
        for (int o = 16; o; o >>= 1) {
            mn = fminf(mn, __shfl_down_sync(0xffffffffu, mn, o));
            mx = fmaxf(mx, __shfl_down_sync(0xffffffffu, mx, o));
        }
        if (lane == 0) {
            float d = mx - mn;
            float c1 = 0.01f * d, c2 = 0.03f * d;
            scr[24] = c1 * c1;
            scr[25] = c2 * c2;
        }
    }

    const float* Pi = P + (size_t)img * IMG_ELEMS;
    const float* Ti = T + (size_t)img * IMG_ELEMS;
    const float* Mi = M + (size_t)img * IMG_ELEMS;

    // ---- Halo load: pair index = lane (pairs 0..31) + extra (32..35, lane<4).
    //      Row = warp + 8*it, it = 0..4 fully unrolled; iterations 0..3 are
    //      unconditional -> compiler batches LDGs (high MLP).
    //      MAE/MSE accumulate on it<4 & main pairs (= owned 64x32 region). ----
    float sa = 0.f, sq = 0.f;
    {
        int rb = warp;                           // base row 0..7
        int cmain = min(ox0 + 2 * lane, W - 2);
        bool has_e = lane < 4;
        int cext = min(ox0 + 64 + 2 * (lane & 3), W - 2);

#pragma unroll
        for (int it = 0; it < 5; it++) {
            int r = rb + it * 8;
            if (it == 4 && r >= HH) continue;    // only last iter predicated
            int gy = min(oy0 + r, H - 1);
            const float2* Pr = (const float2*)(Pi + gy * W);
            const float2* Tr = (const float2*)(Ti + gy * W);
            const float2* Mr = (const float2*)(Mi + gy * W);

            float2 p = Pr[cmain >> 1];
            float2 t = Tr[cmain >> 1];
            float2 m = Mr[cmain >> 1];
            float x0 = p.x * m.x, y0 = t.x * m.x;
            float x1 = p.y * m.y, y1 = t.y * m.y;
            sxy[r * PSXY + lane] = make_float4(x0, y0, x1, y1);
            if (it < 4) {                        // owned region exactly
                float d0 = x0 - y0, d1 = x1 - y1;
                sa += fabsf(d0) + fabsf(d1);
                sq += d0 * d0 + d1 * d1;
            }
            if (has_e) {
                float2 pe = Pr[cext >> 1];
                float2 te = Tr[cext >> 1];
                float2 me = Mr[cext >> 1];
                sxy[r * PSXY + 32 + (lane & 3)] = make_float4(
                    pe.x * me.x, te.x * me.x, pe.y * me.y, te.y * me.y);
            }
        }
    }
    __syncthreads();

    // ---- Horizontal pass: warp w -> 8 output cols [w*8, w*8+8), lane -> row.
    //      Window = pixels cbase..cbase+13 = 7 float4 (2 pixels each). ----
    {
        int cbase = warp * 8;
#pragma unroll
        for (int pass = 0; pass < 2; pass++) {
            int r = pass * 32 + lane;
            if (pass == 1 && lane >= 6) continue;
            const float4* row = sxy + r * PSXY + (cbase >> 1);
            float4 wv[7];
#pragma unroll
            for (int j = 0; j < 7; j++) wv[j] = row[j];

#define PX(p) ((p & 1) ? wv[(p) >> 1].z : wv[(p) >> 1].x)
#define PY(p) ((p & 1) ? wv[(p) >> 1].w : wv[(p) >> 1].y)
            float s0 = 0.f, s1 = 0.f, s2 = 0.f, s3 = 0.f, s4 = 0.f;
#pragma unroll
            for (int j = 0; j < 7; j++) {
                float x = PX(j), y = PY(j);
                s0 += x; s1 += y; s2 += x * x; s3 += y * y; s4 += x * y;
            }
            float4* o4 = hs4 + r * P4 + cbase;
            float*  o1 = hs1 + r * P1 + cbase;
            o4[0] = make_float4(s0, s1, s2, s3);
            o1[0] = s4;
#pragma unroll
            for (int j = 1; j < 8; j++) {
                float xa = PX(6 + j), ya = PY(6 + j);
                float xd = PX(j - 1), yd = PY(j - 1);
                s0 += xa - xd;
                s1 += ya - yd;
                s2 += xa * xa - xd * xd;
                s3 += ya * ya - yd * yd;
                s4 += xa * ya - xd * yd;
                o4[j] = make_float4(s0, s1, s2, s3);
                o1[j] = s4;
            }
#undef PX
#undef PY
        }
    }
    __syncthreads();

    // ---- Vertical pass: thread (tx, ty) -> col tx, rows ty*8..ty*8+7 ----
    int tx = tid & 63;
    int ty = tid >> 6;
    int r0 = ty * 8;

    float C1 = scr[24], C2 = scr[25];
    float4 b4[7]; float b1[7];
    float t0 = 0.f, t1 = 0.f, t2 = 0.f, t3 = 0.f, t4 = 0.f;
    b4[6] = make_float4(0.f, 0.f, 0.f, 0.f); b1[6] = 0.f;
#pragma unroll
    for (int j = 0; j < 6; j++) {
        float4 v = hs4[(r0 + j) * P4 + tx];
        float  u = hs1[(r0 + j) * P1 + tx];
        b4[j] = v; b1[j] = u;
        t0 += v.x; t1 += v.y; t2 += v.z; t3 += v.w; t4 += u;
    }

    const float inv = 1.f / 49.f;
    const float cov = 49.f / 48.f;
    float lsum = 0.f;
    int gox = ox0 + tx;

#pragma unroll
    for (int i = 0; i < 8; i++) {
        int slot = (6 + i) % 7;
        float4 v = hs4[(r0 + 6 + i) * P4 + tx];
        float  u = hs1[(r0 + 6 + i) * P1 + tx];
        t0 += v.x - b4[slot].x;
        t1 += v.y - b4[slot].y;
        t2 += v.z - b4[slot].z;
        t3 += v.w - b4[slot].w;
        t4 += u - b1[slot];
        b4[slot] = v; b1[slot] = u;
        int goy = oy0 + r0 + i;
        if (gox < VALID && goy < VALID) {
            float ux = t0 * inv, uy = t1 * inv;
            float vx  = cov * (t2 * inv - ux * ux);
            float vy  = cov * (t3 * inv - uy * uy);
            float vxy = cov * (t4 * inv - ux * uy);
            float A1 = 2.f * ux * uy + C1;
            float A2 = 2.f * vxy + C2;
            float B1 = ux * ux + uy * uy + C1;
            float B2 = vx + vy + C2;
            lsum += __fdividef(A1 * A2, B1 * B2);
        }
    }

    // ---- Block reduce (sa, sq, lsum) -> partial stores ----
#pragma unroll
    for (int o = 16; o; o >>= 1) {
        sa += __shfl_down_sync(0xffffffffu, sa, o);
        sq += __shfl_down_sync(0xffffffffu, sq, o);
        lsum += __shfl_down_sync(0xffffffffu, lsum, o);
    }
    __syncthreads();
    if (lane == 0) { scr[warp] = sa; scr[8 + warp] = sq; scr[16 + warp] = lsum; }
    __syncthreads();
    if (tid == 0) {
        float A = 0.f, Q = 0.f, S = 0.f;
#pragma unroll
        for (int i = 0; i < 8; i++) { A += scr[i]; Q += scr[8 + i]; S += scr[16 + i]; }
        int bid = blockIdx.x + (blockIdx.y << 3) + (blockIdx.z << 7);
        g_pabs[bid] = A;
        g_psq[bid] = Q;
        g_pS[bid] = S;
    }
}

// ---------------------------------------------------------------------------
// Kernel 3: final reduction of 6144 partials (double) -> 4 outputs
// ---------------------------------------------------------------------------
__global__ void __launch_bounds__(256) k_final(float* __restrict__ out) {
    int tid = threadIdx.x;
    double a = 0.0, q = 0.0, s = 0.0;
    for (int i = tid; i < NBLK; i += 256) {
        a += (double)g_pabs[i];
        q += (double)g_psq[i];
        s += (double)g_pS[i];
    }
#pragma unroll
    for (int o = 16; o; o >>= 1) {
        a += __shfl_down_sync(0xffffffffu, a, o);
        q += __shfl_down_sync(0xffffffffu, q, o);
        s += __shfl_down_sync(0xffffffffu, s, o);
    }
    __shared__ double wa[8], wq[8], ws[8];
    int lane = tid & 31, w = tid >> 5;
    if (lane == 0) { wa[w] = a; wq[w] = q; ws[w] = s; }
    __syncthreads();
    if (tid == 0) {
        double A = 0.0, Q = 0.0, S = 0.0;
#pragma unroll
        for (int i = 0; i < 8; i++) { A += wa[i]; Q += wq[i]; S += ws[i]; }
        double mae = A / N_TOTAL;
        double mse = Q / N_TOTAL;
        double ssim_loss = 1.0 - S / N_SSIM;
        double total = mae + 0.5 * mse + 0.2 * ssim_loss;
        out[0] = (float)total;
        out[1] = (float)mae;
        out[2] = (float)mse;
        out[3] = (float)ssim_loss;
    }
}

// ---------------------------------------------------------------------------
extern "C" void kernel_launch(void* const* d_in, const int* in_sizes, int n_in,
                              void* d_out, int out_size)
{
    const float* y_pred = (const float*)d_in[0];
    const float* y_true = (const float*)d_in[1];
    const float* mask   = (const float*)d_in[2];
    float* out = (float*)d_out;

    cudaFuncSetAttribute(k_ssim, cudaFuncAttributeMaxDynamicSharedMemorySize,
                         SMEM_FLOATS * 4);

    k_range<<<IMGS * RB, 256>>>((const float4*)y_true, (const float4*)mask);
    dim3 grid(GRID_X, GRID_Y, IMGS);
    k_ssim<<<grid, 256, SMEM_FLOATS * 4>>>(y_pred, y_true, mask);
    k_final<<<1, 256>>>(out);
}